// round 6
// baseline (speedup 1.0000x reference)
#include <cuda_runtime.h>

// Problem constants (fixed by the reference)
#define BB     32
#define TXX    4096
#define DD     512
#define SPLITS 32
#define TCHUNK (TXX / SPLITS)   // 128
#define NT     256              // threads per ctx block (2 rows of D per iter)

// Per-batch 1/sum(mask) scratch (no cudaMalloc allowed)
__device__ float g_inv[BB];

// Kernel 0: per-batch mask count -> g_inv, and zero the context region of out.
__global__ void prep_kernel(const int* __restrict__ mask,
                            const int* __restrict__ um_p,
                            float* __restrict__ out) {
    const int b   = blockIdx.x;     // 32 blocks
    const int tid = threadIdx.x;    // 256 threads
    const bool um = (um_p[0] != 0);

    // Vectorized mask count: 4096 ints = 1024 int4 per batch
    const int4* m4 = (const int4*)(mask + b * TXX);
    int cnt = 0;
#pragma unroll
    for (int i = tid; i < TXX / 4; i += 256) {
        int4 v = m4[i];
        cnt += (v.x != 0) + (v.y != 0) + (v.z != 0) + (v.w != 0);
    }

    __shared__ int sdata[256];
    sdata[tid] = cnt;
    __syncthreads();
#pragma unroll
    for (int s = 128; s > 0; s >>= 1) {
        if (tid < s) sdata[tid] += sdata[tid + s];
        __syncthreads();
    }
    if (tid == 0) {
        int c = sdata[0] > 0 ? sdata[0] : 1;
        g_inv[b] = um ? (1.0f / (float)c) : 1.0f;
    }

    // Zero context region out[0 .. B*D) (d_out is poisoned 0xAA)
    for (int i = b * 256 + tid; i < BB * DD; i += 32 * 256)
        out[i] = 0.0f;
}

// Kernel 1: write alpha, ORDERED compaction of kept rows (ballot prefix-sum,
// preserves ascending t for DRAM row locality), masked row-sum with
// unconditional streaming LDG.128 (unroll 8 -> deep MLP), SMEM half-reduction,
// then global atomics.
// Grid: (SPLITS, BB), NT=256 threads; thread -> (half = tid>>7, col = tid&127).
__global__ void __launch_bounds__(NT)
ctx_alpha_kernel(const float* __restrict__ a,
                 const int* __restrict__ mask,
                 const int* __restrict__ um_p,
                 float* __restrict__ out) {
    const int s   = blockIdx.x;
    const int b   = blockIdx.y;
    const int tid = threadIdx.x;
    const bool um = (um_p[0] != 0);
    const float inv = g_inv[b];
    const int t0 = s * TCHUNK;

    __shared__ int    slist[TCHUNK];
    __shared__ int    wcnt[TCHUNK / 32];  // per-warp keep counts (4 warps stage)
    __shared__ int    scnt;
    __shared__ float4 sctx[DD / 4];       // 128 float4

    // Stage: threads 0..127 each own one t. Write alpha; ordered compaction.
    float* alpha = out + BB * DD + (size_t)b * TXX;
    if (tid < TCHUNK) {
        const int lane = tid & 31;
        const int w    = tid >> 5;        // 0..3
        int t = t0 + tid;
        int m = (mask[b * TXX + t] != 0);
        int keep = um ? m : 1;
        alpha[t] = um ? (m ? inv : 0.0f) : 1.0f;

        unsigned ball = __ballot_sync(0xffffffffu, keep);
        if (lane == 0) wcnt[w] = __popc(ball);
        // intra-warp exclusive prefix
        int within = __popc(ball & ((1u << lane) - 1u));
        __syncwarp();
        // need warp offsets -> barrier below, then write
        __syncthreads();
        int off = 0;
#pragma unroll
        for (int i = 0; i < TCHUNK / 32; i++)
            off += (i < w) ? wcnt[i] : 0;
        if (keep) slist[off + within] = tid;
        if (tid == 0) {
            int tot = 0;
#pragma unroll
            for (int i = 0; i < TCHUNK / 32; i++) tot += wcnt[i];
            scnt = tot;
        }
    } else {
        __syncthreads();                   // match the staged barrier
    }
    __syncthreads();

    const int n    = scnt;
    const int col  = tid & 127;
    const int half = tid >> 7;

    // Unconditional streaming loads over the ordered compacted list.
    // unroll 8 -> 8 independent LDG.128 in flight per thread.
    const float4* abase = (const float4*)(a + ((size_t)b * TXX + t0) * DD);
    float4 acc = make_float4(0.f, 0.f, 0.f, 0.f);
#pragma unroll 8
    for (int i = half; i < n; i += 2) {
        int t = slist[i];                       // LDS broadcast within warp
        float4 v = __ldcs(abase + (size_t)t * (DD / 4) + col);
        acc.x += v.x; acc.y += v.y; acc.z += v.z; acc.w += v.w;
    }

    // Reduce the two halves through SMEM, then half 1 issues the atomics.
    if (half == 0) sctx[col] = acc;
    __syncthreads();
    if (half == 1) {
        float4 o = sctx[col];
        acc.x += o.x; acc.y += o.y; acc.z += o.z; acc.w += o.w;
        float* ctx = out + (size_t)b * DD + col * 4;
        atomicAdd(ctx + 0, acc.x * inv);
        atomicAdd(ctx + 1, acc.y * inv);
        atomicAdd(ctx + 2, acc.z * inv);
        atomicAdd(ctx + 3, acc.w * inv);
    }
}

extern "C" void kernel_launch(void* const* d_in, const int* in_sizes, int n_in,
                              void* d_out, int out_size) {
    // metadata order: a, h, coverage, X_mask, Wa, Wh, Wc, V, use_coverage, use_masking
    const float* a    = (const float*)d_in[0];
    const int*   mask = (const int*)  d_in[3];
    const int*   um   = (const int*)  d_in[9];
    float* out = (float*)d_out;

    prep_kernel<<<BB, 256>>>(mask, um, out);
    dim3 grid(SPLITS, BB);
    ctx_alpha_kernel<<<grid, NT>>>(a, mask, um, out);
}

// round 8
// speedup vs baseline: 1.0868x; 1.0868x over previous
#include <cuda_runtime.h>

// Problem constants (fixed by the reference)
#define BB     32
#define TXX    4096
#define DD     512
#define SPLITS 32
#define TCHUNK (TXX / SPLITS)   // 128
#define NT     256              // threads per ctx block (2 rows of D per iter)

// Per-batch 1/sum(mask) scratch (no cudaMalloc allowed)
__device__ float g_inv[BB];

// Kernel 0: per-batch mask count -> g_inv, and zero the context region of out.
__global__ void prep_kernel(const int* __restrict__ mask,
                            const int* __restrict__ um_p,
                            float* __restrict__ out) {
    const int b   = blockIdx.x;     // 32 blocks
    const int tid = threadIdx.x;    // 256 threads
    const bool um = (um_p[0] != 0);

    // Vectorized mask count: 4096 ints = 1024 int4 per batch
    const int4* m4 = (const int4*)(mask + b * TXX);
    int cnt = 0;
#pragma unroll
    for (int i = tid; i < TXX / 4; i += 256) {
        int4 v = m4[i];
        cnt += (v.x != 0) + (v.y != 0) + (v.z != 0) + (v.w != 0);
    }

    __shared__ int sdata[256];
    sdata[tid] = cnt;
    __syncthreads();
#pragma unroll
    for (int s = 128; s > 0; s >>= 1) {
        if (tid < s) sdata[tid] += sdata[tid + s];
        __syncthreads();
    }
    if (tid == 0) {
        int c = sdata[0] > 0 ? sdata[0] : 1;
        g_inv[b] = um ? (1.0f / (float)c) : 1.0f;
    }

    // Zero context region out[0 .. B*D) (d_out is poisoned 0xAA)
    for (int i = b * 256 + tid; i < BB * DD; i += 32 * 256)
        out[i] = 0.0f;
}

// Kernel 1: write alpha, ORDERED compaction of kept rows (ballot prefix-sum,
// ascending t for DRAM row locality; all barriers at top level), masked
// row-sum with unconditional LDG.128 (unroll 4, as in the proven R4 kernel),
// SMEM half-reduction, then global atomics.
// Grid: (SPLITS, BB), NT=256 threads; thread -> (half = tid>>7, col = tid&127).
__global__ void __launch_bounds__(NT)
ctx_alpha_kernel(const float* __restrict__ a,
                 const int* __restrict__ mask,
                 const int* __restrict__ um_p,
                 float* __restrict__ out) {
    const int s   = blockIdx.x;
    const int b   = blockIdx.y;
    const int tid = threadIdx.x;
    const bool um = (um_p[0] != 0);
    const float inv = g_inv[b];
    const int t0 = s * TCHUNK;

    __shared__ int    slist[TCHUNK];
    __shared__ int    wcnt[TCHUNK / 32];  // 4 staging warps
    __shared__ int    scnt;
    __shared__ float4 sctx[DD / 4];       // 128 float4

    // Stage A: threads 0..127 own one t each; write alpha, ballot keep bits.
    float* alpha = out + BB * DD + (size_t)b * TXX;
    int keep = 0;
    unsigned ball = 0;
    if (tid < TCHUNK) {
        int t = t0 + tid;
        int m = (mask[b * TXX + t] != 0);
        keep = um ? m : 1;
        alpha[t] = um ? (m ? inv : 0.0f) : 1.0f;
        ball = __ballot_sync(0xffffffffu, keep);
        if ((tid & 31) == 0) wcnt[tid >> 5] = __popc(ball);
    }
    __syncthreads();   // top-level barrier (no divergence)

    // Stage B: ordered write of compacted indices.
    if (tid < TCHUNK) {
        const int lane = tid & 31;
        const int w    = tid >> 5;
        int off = 0;
#pragma unroll
        for (int i = 0; i < TCHUNK / 32; i++)
            off += (i < w) ? wcnt[i] : 0;
        int within = __popc(ball & ((1u << lane) - 1u));
        if (keep) slist[off + within] = tid;
        if (tid == 0)
            scnt = wcnt[0] + wcnt[1] + wcnt[2] + wcnt[3];
    }
    __syncthreads();   // top-level barrier

    const int n    = scnt;
    const int col  = tid & 127;
    const int half = tid >> 7;

    // Unconditional loads over the ORDERED compacted list (ascending t ->
    // sequential 2KB-row bursts). unroll 4, plain loads — identical mainloop
    // shape to the proven R4 kernel.
    const float4* abase = (const float4*)(a + ((size_t)b * TXX + t0) * DD);
    float4 acc = make_float4(0.f, 0.f, 0.f, 0.f);
#pragma unroll 4
    for (int i = half; i < n; i += 2) {
        int t = slist[i];                       // LDS broadcast within warp
        float4 v = abase[(size_t)t * (DD / 4) + col];
        acc.x += v.x; acc.y += v.y; acc.z += v.z; acc.w += v.w;
    }

    // Reduce the two halves through SMEM, then half 1 issues the atomics.
    if (half == 0) sctx[col] = acc;
    __syncthreads();
    if (half == 1) {
        float4 o = sctx[col];
        acc.x += o.x; acc.y += o.y; acc.z += o.z; acc.w += o.w;
        float* ctx = out + (size_t)b * DD + col * 4;
        atomicAdd(ctx + 0, acc.x * inv);
        atomicAdd(ctx + 1, acc.y * inv);
        atomicAdd(ctx + 2, acc.z * inv);
        atomicAdd(ctx + 3, acc.w * inv);
    }
}

extern "C" void kernel_launch(void* const* d_in, const int* in_sizes, int n_in,
                              void* d_out, int out_size) {
    // metadata order: a, h, coverage, X_mask, Wa, Wh, Wc, V, use_coverage, use_masking
    const float* a    = (const float*)d_in[0];
    const int*   mask = (const int*)  d_in[3];
    const int*   um   = (const int*)  d_in[9];
    float* out = (float*)d_out;

    prep_kernel<<<BB, 256>>>(mask, um, out);
    dim3 grid(SPLITS, BB);
    ctx_alpha_kernel<<<grid, NT>>>(a, mask, um, out);
}